// round 1
// baseline (speedup 1.0000x reference)
#include <cuda_runtime.h>
#include <math.h>

// ---------------------------------------------------------------------------
// VideoAttention: b=2, t=8, C=768, h=w=16 -> hw=256, S=2048, heads=12, c=64
// Pipeline:
//   K1 norm_k   : EDM2 MP weight normalization (w_qkv 2304 rows, w_proj 768)
//   K2 gemm_k<0>: QKV = Wn @ X  (2304 x 4096 x 768), scatter to q/k/v [b,m,s,c]
//   K3 rope_k   : rotary over frame index on q,k
//   K4 flash_k  : block-causal flash attention (frame-aligned -> pure loop bound)
//                 epilogue writes O transposed into proj-B layout [bt][cc*12+m][p]
//   K5 gemm_k<1>: proj GEMM (768 x 4096 x 768) + mp_sum residual -> d_out
// fp32 everywhere; inner loops use packed fma.rn.f32x2 (FFMA2, 2x fp32 rate).
// ---------------------------------------------------------------------------

#define NB   2
#define NT   8
#define NM   12
#define HD   64
#define C3   2304
#define CDIM 768
#define HW   256
#define SLEN 2048
#define BT   16
#define XSTRIDE 196608   // 768*256, per-bt stride in x / yt

__device__ float g_wqkv[C3 * CDIM];
__device__ float g_wproj[CDIM * CDIM];
__device__ float g_q[NB * NM * SLEN * HD];
__device__ float g_k[NB * NM * SLEN * HD];
__device__ float g_v[NB * NM * SLEN * HD];
__device__ float g_yt[BT * CDIM * HW];   // attention out in proj-B layout

// ---------------- f32x2 helpers (FFMA2) ----------------
__device__ __forceinline__ unsigned long long pack2(float x) {
    unsigned long long r;
    asm("mov.b64 %0, {%1, %1};" : "=l"(r) : "f"(x));
    return r;
}
__device__ __forceinline__ unsigned long long f2u(float x, float y) {
    unsigned long long r;
    asm("mov.b64 %0, {%1, %2};" : "=l"(r) : "f"(x), "f"(y));
    return r;
}
__device__ __forceinline__ float2 u2f(unsigned long long v) {
    float2 f;
    asm("mov.b64 {%0, %1}, %2;" : "=f"(f.x), "=f"(f.y) : "l"(v));
    return f;
}
__device__ __forceinline__ void ffma2(unsigned long long& d,
                                      unsigned long long a, unsigned long long b) {
    asm("fma.rn.f32x2 %0, %1, %2, %0;" : "+l"(d) : "l"(a), "l"(b));
}
__device__ __forceinline__ void fmul2(unsigned long long& d, unsigned long long c) {
    asm("mul.rn.f32x2 %0, %0, %1;" : "+l"(d) : "l"(c));
}
__device__ __forceinline__ unsigned long long flo(float4 v) { return f2u(v.x, v.y); }
__device__ __forceinline__ unsigned long long fhi(float4 v) { return f2u(v.z, v.w); }
__device__ __forceinline__ float f4get(float4 v, int i) {
    return i == 0 ? v.x : i == 1 ? v.y : i == 2 ? v.z : v.w;
}

// ---------------- K1: weight normalization ----------------
// w_n = w / (sqrt(768)*eps + ||row||)   (algebraically == reference)
__global__ __launch_bounds__(256) void norm_k(const float* __restrict__ wqkv,
                                              const float* __restrict__ wproj) {
    int row = blockIdx.x;
    const float* src;
    float* dst;
    if (row < C3) { src = wqkv + row * CDIM;        dst = g_wqkv + row * CDIM; }
    else          { src = wproj + (row - C3) * CDIM; dst = g_wproj + (row - C3) * CDIM; }

    float ss = 0.f;
    for (int i = threadIdx.x; i < CDIM; i += 256) { float v = src[i]; ss = fmaf(v, v, ss); }
    #pragma unroll
    for (int off = 16; off; off >>= 1) ss += __shfl_xor_sync(0xffffffffu, ss, off);

    __shared__ float sred[8];
    __shared__ float sscale;
    if ((threadIdx.x & 31) == 0) sred[threadIdx.x >> 5] = ss;
    __syncthreads();
    if (threadIdx.x == 0) {
        float t = 0.f;
        #pragma unroll
        for (int i = 0; i < 8; i++) t += sred[i];
        float nrm = sqrtf(t);
        sscale = 1.0f / (sqrtf(768.0f) * 1e-4f + nrm);
    }
    __syncthreads();
    float sc = sscale;
    for (int i = threadIdx.x; i < CDIM; i += 256) dst[i] = src[i] * sc;
}

// ---------------- K2/K5: shared 128x128x768 GEMM ----------------
// EPI=0: A=g_wqkv, B=x,    scatter to q/k/v with (3,m,c) split of the o dim
// EPI=1: A=g_wproj, B=g_yt, epilogue = mp_sum residual into Out
template <int EPI>
__global__ __launch_bounds__(256) void gemm_k(const float* __restrict__ Bx,
                                              const float* __restrict__ Xres,
                                              float* __restrict__ Out) {
    __shared__ float As[16 * 128];
    __shared__ float Bs[16 * 128];

    const int tid = threadIdx.x;
    const int tx = tid & 15, ty = tid >> 4;
    const int o0 = blockIdx.y * 128;
    const int n0 = blockIdx.x * 128;
    const int bt = n0 >> 8;
    const int p0 = n0 & 255;

    const float* A = (EPI == 0) ? g_wqkv : g_wproj;
    const float* Bm = (EPI == 0) ? Bx : g_yt;

    unsigned long long acc[4][8];
    #pragma unroll
    for (int i = 0; i < 4; i++)
        #pragma unroll
        for (int j = 0; j < 8; j++) acc[i][j] = 0ULL;

    const int ml = tid >> 1;
    const int kh = (tid & 1) * 8;
    const float* Ag = A + (o0 + ml) * CDIM + kh;
    const float* Bg = Bm + bt * XSTRIDE + p0;

    for (int kc = 0; kc < CDIM; kc += 16) {
        __syncthreads();
        // A tile (transposed store: As[k][m])
        float4 a0 = *(const float4*)(Ag + kc);
        float4 a1 = *(const float4*)(Ag + kc + 4);
        As[(kh + 0) * 128 + ml] = a0.x; As[(kh + 1) * 128 + ml] = a0.y;
        As[(kh + 2) * 128 + ml] = a0.z; As[(kh + 3) * 128 + ml] = a0.w;
        As[(kh + 4) * 128 + ml] = a1.x; As[(kh + 5) * 128 + ml] = a1.y;
        As[(kh + 6) * 128 + ml] = a1.z; As[(kh + 7) * 128 + ml] = a1.w;
        // B tile (as-is: Bs[k][n])
        {
            int k = tid >> 5, n4 = tid & 31;
            *(float4*)&Bs[k * 128 + n4 * 4] = *(const float4*)(Bg + (kc + k) * 256 + n4 * 4);
        }
        {
            int slot = tid + 256;
            int k = slot >> 5, n4 = slot & 31;
            *(float4*)&Bs[k * 128 + n4 * 4] = *(const float4*)(Bg + (kc + k) * 256 + n4 * 4);
        }
        __syncthreads();
        #pragma unroll
        for (int k = 0; k < 16; k++) {
            unsigned long long a2[4];
            #pragma unroll
            for (int i = 0; i < 4; i++)
                a2[i] = *(const unsigned long long*)&As[k * 128 + ty * 8 + 2 * i];
            #pragma unroll
            for (int j = 0; j < 8; j++) {
                unsigned long long bb = pack2(Bs[k * 128 + tx * 8 + j]);
                ffma2(acc[0][j], a2[0], bb);
                ffma2(acc[1][j], a2[1], bb);
                ffma2(acc[2][j], a2[2], bb);
                ffma2(acc[3][j], a2[3], bb);
            }
        }
    }

    if (EPI == 0) {
        const int bb = bt >> 3, ti = bt & 7;
        #pragma unroll
        for (int i = 0; i < 4; i++) {
            int o = o0 + ty * 8 + 2 * i;
            int qi = o / CDIM;
            int rem = o - qi * CDIM;
            int mh = rem >> 6, cc = rem & 63;
            float* dst = (qi == 0) ? g_q : (qi == 1) ? g_k : g_v;
            int base = ((bb * NM + mh) * SLEN + ti * 256 + p0 + tx * 8) * HD + cc;
            #pragma unroll
            for (int j = 0; j < 8; j++) {
                float2 v = u2f(acc[i][j]);
                *(float2*)&dst[base + j * HD] = v;
            }
        }
    } else {
        const float c1 = 0.9191450300180578f;   // 0.7 / sqrt(0.58)
        const float c2 = 0.3939192985791676f;   // 0.3 / sqrt(0.58)
        #pragma unroll
        for (int i = 0; i < 4; i++) {
            int o = o0 + ty * 8 + 2 * i;
            int idx0 = bt * XSTRIDE + o * 256 + p0 + tx * 8;
            #pragma unroll
            for (int j = 0; j < 8; j++) {
                float2 v = u2f(acc[i][j]);
                Out[idx0 + j]       = Xres[idx0 + j] * c1 + v.x * c2;
                Out[idx0 + 256 + j] = Xres[idx0 + 256 + j] * c1 + v.y * c2;
            }
        }
    }
}

// ---------------- K3: RoPE over frame index ----------------
__global__ __launch_bounds__(256) void rope_k() {
    int idx = blockIdx.x * 256 + threadIdx.x;   // < 2*12*2048*32
    int d2 = idx & 31;
    int s = (idx >> 5) & 2047;
    int bm = idx >> 16;
    int ti = s >> 8;
    float ang = (float)ti * __powf(10000.0f, -(float)d2 * (1.0f / 32.0f));
    float sn, cs;
    __sincosf(ang, &sn, &cs);
    int base = (bm * SLEN + s) * HD + d2;
    float q1 = g_q[base], q2 = g_q[base + 32];
    g_q[base]      = q1 * cs - q2 * sn;
    g_q[base + 32] = q1 * sn + q2 * cs;
    float k1 = g_k[base], k2 = g_k[base + 32];
    g_k[base]      = k1 * cs - k2 * sn;
    g_k[base + 32] = k1 * sn + k2 * cs;
}

// ---------------- K4: block-causal flash attention ----------------
// grid (32 q-tiles, 24 bm). 64-row q tile, 32-key chunks, c=64.
// thread map: tx = tid&15, ty = tid>>4; q rows = ty*4+ri, keys j = tx+16*ji.
__global__ __launch_bounds__(256) void flash_k() {
    __shared__ float Qs[64 * 68];
    __shared__ float Ks[32 * 68];
    __shared__ float Vs[32 * 68];
    __shared__ float Ps[64 * 36];

    const int tid = threadIdx.x;
    const int tx = tid & 15, ty = tid >> 4;
    const int qt = blockIdx.x, bm = blockIdx.y;
    const int s0 = qt * 64;
    const int fr = qt >> 2;                  // frame of this q tile
    const int nk = (fr + 1) * 256;           // causal key count (frame-aligned)

    const float* Qg = g_q + (bm * SLEN + s0) * HD;
    const float* Kg = g_k + bm * SLEN * HD;
    const float* Vg = g_v + bm * SLEN * HD;

    #pragma unroll
    for (int it = 0; it < 4; it++) {
        int slot = tid + it * 256;
        int r = slot >> 4, c4 = slot & 15;
        *(float4*)&Qs[r * 68 + c4 * 4] = *(const float4*)&Qg[r * 64 + c4 * 4];
    }

    float mrow[4], lrow[4];
    unsigned long long oac[4][2];
    #pragma unroll
    for (int ri = 0; ri < 4; ri++) {
        mrow[ri] = -1e30f;
        lrow[ri] = 0.f;
        oac[ri][0] = 0ULL;
        oac[ri][1] = 0ULL;
    }

    for (int k0 = 0; k0 < nk; k0 += 32) {
        __syncthreads();
        #pragma unroll
        for (int it = 0; it < 2; it++) {
            int slot = tid + it * 256;
            int r = slot >> 4, c4 = slot & 15;
            *(float4*)&Ks[r * 68 + c4 * 4] = *(const float4*)&Kg[(k0 + r) * 64 + c4 * 4];
            *(float4*)&Vs[r * 68 + c4 * 4] = *(const float4*)&Vg[(k0 + r) * 64 + c4 * 4];
        }
        __syncthreads();

        // S = Q K^T (f32x2 pairs along c, horizontal add at the end)
        unsigned long long sac[4][2];
        #pragma unroll
        for (int ri = 0; ri < 4; ri++) { sac[ri][0] = 0ULL; sac[ri][1] = 0ULL; }
        #pragma unroll
        for (int c = 0; c < 64; c += 4) {
            float4 q4[4], k4[2];
            #pragma unroll
            for (int ri = 0; ri < 4; ri++) q4[ri] = *(const float4*)&Qs[(ty * 4 + ri) * 68 + c];
            #pragma unroll
            for (int ji = 0; ji < 2; ji++) k4[ji] = *(const float4*)&Ks[(tx + 16 * ji) * 68 + c];
            #pragma unroll
            for (int ri = 0; ri < 4; ri++) {
                #pragma unroll
                for (int ji = 0; ji < 2; ji++) {
                    ffma2(sac[ri][ji], flo(q4[ri]), flo(k4[ji]));
                    ffma2(sac[ri][ji], fhi(q4[ri]), fhi(k4[ji]));
                }
            }
        }
        float sc[4][2];
        #pragma unroll
        for (int ri = 0; ri < 4; ri++) {
            #pragma unroll
            for (int ji = 0; ji < 2; ji++) {
                float2 t = u2f(sac[ri][ji]);
                sc[ri][ji] = (t.x + t.y) * 0.125f;   // 1/sqrt(64)
            }
        }

        // online softmax (row reductions across the 16 tx lanes)
        float pr[4][2];
        #pragma unroll
        for (int ri = 0; ri < 4; ri++) {
            float mx = fmaxf(sc[ri][0], sc[ri][1]);
            #pragma unroll
            for (int off = 8; off; off >>= 1) mx = fmaxf(mx, __shfl_xor_sync(0xffffffffu, mx, off));
            float mnew = fmaxf(mrow[ri], mx);
            float cr = __expf(mrow[ri] - mnew);
            mrow[ri] = mnew;
            float p0 = __expf(sc[ri][0] - mnew);
            float p1 = __expf(sc[ri][1] - mnew);
            pr[ri][0] = p0; pr[ri][1] = p1;
            float ps = p0 + p1;
            #pragma unroll
            for (int off = 8; off; off >>= 1) ps += __shfl_xor_sync(0xffffffffu, ps, off);
            lrow[ri] = lrow[ri] * cr + ps;
            unsigned long long cp = pack2(cr);
            fmul2(oac[ri][0], cp);
            fmul2(oac[ri][1], cp);
        }
        // stage P through smem (same half-warp writes & reads -> syncwarp only)
        #pragma unroll
        for (int ri = 0; ri < 4; ri++) {
            Ps[(ty * 4 + ri) * 36 + tx]      = pr[ri][0];
            Ps[(ty * 4 + ri) * 36 + tx + 16] = pr[ri][1];
        }
        __syncwarp();

        // O += P V : channels of this thread = {2tx,2tx+1} and {2tx+32,2tx+33}
        #pragma unroll
        for (int j4 = 0; j4 < 32; j4 += 4) {
            float4 a4[4];
            #pragma unroll
            for (int ri = 0; ri < 4; ri++) a4[ri] = *(const float4*)&Ps[(ty * 4 + ri) * 36 + j4];
            #pragma unroll
            for (int jj = 0; jj < 4; jj++) {
                unsigned long long blo = *(const unsigned long long*)&Vs[(j4 + jj) * 68 + 2 * tx];
                unsigned long long bhi = *(const unsigned long long*)&Vs[(j4 + jj) * 68 + 2 * tx + 32];
                #pragma unroll
                for (int ri = 0; ri < 4; ri++) {
                    unsigned long long ap = pack2(f4get(a4[ri], jj));
                    ffma2(oac[ri][0], ap, blo);
                    ffma2(oac[ri][1], ap, bhi);
                }
            }
        }
    }

    // finalize: O /= l, transpose-stage into Qs as [ch][row]
    __syncthreads();
    #pragma unroll
    for (int ri = 0; ri < 4; ri++) {
        float li = 1.0f / lrow[ri];
        float2 v0 = u2f(oac[ri][0]);
        float2 v1 = u2f(oac[ri][1]);
        int r = ty * 4 + ri;
        Qs[(2 * tx) * 68 + r]      = v0.x * li;
        Qs[(2 * tx + 1) * 68 + r]  = v0.y * li;
        Qs[(2 * tx + 32) * 68 + r] = v1.x * li;
        Qs[(2 * tx + 33) * 68 + r] = v1.y * li;
    }
    __syncthreads();

    // write to proj-B layout: g_yt[bt][ch*12+mh][p], coalesced 64-float runs
    const int bb = bm / NM, mh = bm - bb * NM;
    const int bt = bb * NT + fr;
    const int p0 = s0 & 255;
    int obase = bt * XSTRIDE + mh * 256 + p0;
    #pragma unroll
    for (int it = 0; it < 16; it++) {
        int slot = tid + it * 256;
        int ch = slot >> 6, pp = slot & 63;
        g_yt[obase + ch * 3072 + pp] = Qs[ch * 68 + pp];
    }
}

// ---------------- launch ----------------
extern "C" void kernel_launch(void* const* d_in, const int* in_sizes, int n_in,
                              void* d_out, int out_size) {
    const float* x = (const float*)d_in[0];
    const float* wqkv = (const float*)d_in[1];
    const float* wproj = (const float*)d_in[2];
    float* out = (float*)d_out;

    norm_k<<<C3 + CDIM, 256>>>(wqkv, wproj);
    gemm_k<0><<<dim3(32, 18), 256>>>(x, nullptr, nullptr);
    rope_k<<<(NB * NM * SLEN * 32) / 256, 256>>>();
    flash_k<<<dim3(32, 24), 256>>>();
    gemm_k<1><<<dim3(32, 6), 256>>>(nullptr, x, out);
}

// round 7
// speedup vs baseline: 1.1409x; 1.1409x over previous
#include <cuda_runtime.h>
#include <cuda_bf16.h>
#include <math.h>
#include <cstdint>

// ---------------------------------------------------------------------------
// VideoAttention: b=2, t=8, C=768, h=w=16 -> hw=256, S=2048, heads=12, c=64
//   K1 norm_k    : EDM2 MP weight norm -> fp32 normalized weights
//   K2 gemm_f3<0>: 3xTF32 HMMA GEMM (2304 x 4096 x 768) -> q/k/v fp32
//   K3 rope_k    : rotary over frame index
//   K4 flash_k   : block-causal flash attention (fp32 FFMA2) -> g_yt
//   K5 gemm_f3<1>: 3xTF32 HMMA proj GEMM + mp_sum residual -> out
// 3xTF32: a = ah + al (tf32, split in-register), C = AhBh + AhBl + AlBh
// (~1e-7 rel). Operands remain fp32 in memory; B consumed in native [k][p]
// layout (no transpose / prep kernels).
// ---------------------------------------------------------------------------

#define NB   2
#define NT   8
#define NM   12
#define HD   64
#define C3   2304
#define CDIM 768
#define SLEN 2048
#define BT   16
#define XSTRIDE 196608   // 768*256

__device__ float g_wqkv[C3 * CDIM];
__device__ float g_wproj[CDIM * CDIM];
__device__ float g_q[NB * NM * SLEN * HD];
__device__ float g_k[NB * NM * SLEN * HD];
__device__ float g_v[NB * NM * SLEN * HD];
__device__ float g_yt[BT * CDIM * 256];           // attn out, [bt][ch][p] fp32

// ======================= PTX helpers ===================
__device__ __forceinline__ uint32_t smem_to_u32(const void* p) {
    uint32_t a;
    asm("{ .reg .u64 t; cvta.to.shared.u64 t, %1; cvt.u32.u64 %0, t; }" : "=r"(a) : "l"(p));
    return a;
}
__device__ __forceinline__ float lds_f32(uint32_t addr) {
    float v;
    asm volatile("ld.shared.f32 %0, [%1];" : "=f"(v) : "r"(addr));
    return v;
}
__device__ __forceinline__ void cp16(uint32_t dst, const void* src) {
    asm volatile("cp.async.cg.shared.global [%0], [%1], 16;" :: "r"(dst), "l"(src));
}
#define CP_COMMIT() asm volatile("cp.async.commit_group;" ::: "memory")
#define CP_WAIT(n)  asm volatile("cp.async.wait_group %0;" :: "n"(n) : "memory")

__device__ __forceinline__ uint32_t f2tf32(float a) {
    uint32_t r;
    asm("cvt.rna.tf32.f32 %0, %1;" : "=r"(r) : "f"(a));
    return r;
}
// split fp32 -> tf32 hi + tf32 lo
__device__ __forceinline__ void tf32_split(float a, uint32_t& h, uint32_t& l) {
    h = f2tf32(a);
    l = f2tf32(a - __uint_as_float(h));
}
__device__ __forceinline__ void mma_tf32(float (&d)[4], const uint32_t (&a)[4],
                                         uint32_t b0, uint32_t b1) {
    asm volatile("mma.sync.aligned.m16n8k8.row.col.f32.tf32.tf32.f32 "
                 "{%0,%1,%2,%3}, {%4,%5,%6,%7}, {%8,%9}, {%0,%1,%2,%3};"
                 : "+f"(d[0]), "+f"(d[1]), "+f"(d[2]), "+f"(d[3])
                 : "r"(a[0]), "r"(a[1]), "r"(a[2]), "r"(a[3]), "r"(b0), "r"(b1));
}

// ---------------- f32x2 helpers (flash kernel, FFMA2) ----------------
__device__ __forceinline__ unsigned long long pack2(float x) {
    unsigned long long r; asm("mov.b64 %0, {%1, %1};" : "=l"(r) : "f"(x)); return r;
}
__device__ __forceinline__ unsigned long long f2u(float x, float y) {
    unsigned long long r; asm("mov.b64 %0, {%1, %2};" : "=l"(r) : "f"(x), "f"(y)); return r;
}
__device__ __forceinline__ float2 u2f(unsigned long long v) {
    float2 f; asm("mov.b64 {%0, %1}, %2;" : "=f"(f.x), "=f"(f.y) : "l"(v)); return f;
}
__device__ __forceinline__ void ffma2(unsigned long long& d,
                                      unsigned long long a, unsigned long long b) {
    asm("fma.rn.f32x2 %0, %1, %2, %0;" : "+l"(d) : "l"(a), "l"(b));
}
__device__ __forceinline__ void fmul2(unsigned long long& d, unsigned long long c) {
    asm("mul.rn.f32x2 %0, %0, %1;" : "+l"(d) : "l"(c));
}
__device__ __forceinline__ unsigned long long flo(float4 v) { return f2u(v.x, v.y); }
__device__ __forceinline__ unsigned long long fhi(float4 v) { return f2u(v.z, v.w); }
__device__ __forceinline__ float f4get(float4 v, int i) {
    return i == 0 ? v.x : i == 1 ? v.y : i == 2 ? v.z : v.w;
}

// ---------------- K1: weight normalization (fp32 out) ----------------
__global__ __launch_bounds__(256) void norm_k(const float* __restrict__ wqkv,
                                              const float* __restrict__ wproj) {
    int row = blockIdx.x;
    const float* src;
    float* dst;
    if (row < C3) { src = wqkv + row * CDIM;        dst = g_wqkv + row * CDIM; }
    else          { src = wproj + (row - C3) * CDIM; dst = g_wproj + (row - C3) * CDIM; }

    float ss = 0.f;
    for (int i = threadIdx.x; i < CDIM; i += 256) { float v = src[i]; ss = fmaf(v, v, ss); }
    #pragma unroll
    for (int off = 16; off; off >>= 1) ss += __shfl_xor_sync(0xffffffffu, ss, off);

    __shared__ float sred[8];
    __shared__ float sscale;
    if ((threadIdx.x & 31) == 0) sred[threadIdx.x >> 5] = ss;
    __syncthreads();
    if (threadIdx.x == 0) {
        float t = 0.f;
        #pragma unroll
        for (int i = 0; i < 8; i++) t += sred[i];
        sscale = 1.0f / (sqrtf(768.0f) * 1e-4f + sqrtf(t));
    }
    __syncthreads();
    float sc = sscale;
    for (int i = threadIdx.x; i < CDIM; i += 256) dst[i] = src[i] * sc;
}

// ---------------- K2/K5: 3xTF32 HMMA GEMM, 128x128 block tile --------------
// A = weights [o][k] fp32 (row-major). B = x / g_yt [bt][k][p] fp32 -> staged
// as [k][n] (n = token within bt), i.e. col-major B for mma .row.col.
// smem per stage: A 128 rows x 36 floats (pad 4) | B 32 rows x 132 floats.
// 8 warps: wr = wid&3 -> rows wr*32..+32, wc = wid>>2 -> cols wc*64..+64.
#define A_PAD_W 36
#define B_PAD_W 132
#define A_BYTES (128 * A_PAD_W * 4)          // 18432
#define STAGE_BYTES (A_BYTES + 32 * B_PAD_W * 4)  // 18432 + 16896 = 35328

template <int EPI>
__global__ __launch_bounds__(256) void gemm_f3(const float* __restrict__ Bsrc,
                                               const float* __restrict__ Xres,
                                               float* __restrict__ Out) {
    extern __shared__ char smem[];
    const uint32_t sb = smem_to_u32(smem);
    const int tid = threadIdx.x, wid = tid >> 5, lid = tid & 31;
    const int o0 = blockIdx.y * 128;
    const int n0 = blockIdx.x * 128;
    const int bt = n0 >> 8;
    const int pb = n0 & 255;

    const float* Aw = (EPI == 0 ? g_wqkv : g_wproj) + o0 * CDIM;
    const float* Bg = Bsrc + bt * XSTRIDE + pb;

    float acc[2][8][4];
    #pragma unroll
    for (int mi = 0; mi < 2; mi++)
        #pragma unroll
        for (int ni = 0; ni < 8; ni++)
            #pragma unroll
            for (int d = 0; d < 4; d++) acc[mi][ni][d] = 0.f;

    const int wr = wid & 3, wc = wid >> 2;
    const int g = lid >> 2, tg = lid & 3;

    // stage one 32-k chunk: A[128][32] + B[32][128]
    auto copy_stage = [&](int st, int kc) {
        uint32_t s0 = sb + st * STAGE_BYTES;
        #pragma unroll
        for (int i = 0; i < 4; i++) {          // A: 1024 x 16B
            int idx = tid + i * 256;
            int row = idx >> 3, u = idx & 7;
            cp16(s0 + row * (A_PAD_W * 4) + u * 16,
                 Aw + row * CDIM + kc + u * 4);
        }
        uint32_t sB0 = s0 + A_BYTES;
        #pragma unroll
        for (int i = 0; i < 4; i++) {          // B: 1024 x 16B
            int idx = tid + i * 256;
            int r = idx >> 5, u = idx & 31;
            cp16(sB0 + r * (B_PAD_W * 4) + u * 16,
                 Bg + (kc + r) * 256 + u * 4);
        }
        CP_COMMIT();
    };

    copy_stage(0, 0);
    int st = 0;
    for (int kc = 0; kc < CDIM; kc += 32, st ^= 1) {
        if (kc + 32 < CDIM) {
            copy_stage(st ^ 1, kc + 32);
            CP_WAIT(1);
        } else {
            CP_WAIT(0);
        }
        __syncthreads();

        const uint32_t sA = sb + st * STAGE_BYTES;
        const uint32_t sB = sA + A_BYTES;
        #pragma unroll
        for (int ks = 0; ks < 4; ks++) {
            const int kk = ks * 8;
            // A fragments: rows wr*32 + mi*16 + {g, g+8}, k = kk + {tg, tg+4}
            uint32_t ah[2][4], al[2][4];
            #pragma unroll
            for (int mi = 0; mi < 2; mi++) {
                uint32_t r0 = sA + (wr * 32 + mi * 16 + g) * (A_PAD_W * 4);
                uint32_t r8 = r0 + 8 * (A_PAD_W * 4);
                tf32_split(lds_f32(r0 + (kk + tg) * 4),     ah[mi][0], al[mi][0]);
                tf32_split(lds_f32(r8 + (kk + tg) * 4),     ah[mi][1], al[mi][1]);
                tf32_split(lds_f32(r0 + (kk + tg + 4) * 4), ah[mi][2], al[mi][2]);
                tf32_split(lds_f32(r8 + (kk + tg + 4) * 4), ah[mi][3], al[mi][3]);
            }
            #pragma unroll
            for (int ni = 0; ni < 8; ni++) {
                // B fragment: n = wc*64 + ni*8 + g, k = kk + {tg, tg+4}
                const int n = wc * 64 + ni * 8 + g;
                uint32_t b0h, b0l, b1h, b1l;
                tf32_split(lds_f32(sB + (kk + tg) * (B_PAD_W * 4) + n * 4), b0h, b0l);
                tf32_split(lds_f32(sB + (kk + tg + 4) * (B_PAD_W * 4) + n * 4), b1h, b1l);
                #pragma unroll
                for (int mi = 0; mi < 2; mi++) {
                    mma_tf32(acc[mi][ni], ah[mi], b0h, b1h);
                    mma_tf32(acc[mi][ni], ah[mi], b0l, b1l);
                    mma_tf32(acc[mi][ni], al[mi], b0h, b1h);
                }
            }
        }
        __syncthreads();
    }

    // ---- epilogue (C frag: d0,d1 -> row g, cols 2tg,2tg+1; d2,d3 -> row g+8) ----
    const int rB = g;
    const int cB = tg * 2;

    if (EPI == 0) {
        const int qi = blockIdx.y / 6;          // 768/128 = 6 blocks per q/k/v
        float* dst = (qi == 0) ? g_q : (qi == 1) ? g_k : g_v;
        const int rem0 = o0 - qi * CDIM + wr * 32;
        const int bb = bt >> 3, ti = bt & 7;
        #pragma unroll
        for (int mi = 0; mi < 2; mi++)
            #pragma unroll
            for (int dd = 0; dd < 2; dd++) {
                int rem = rem0 + mi * 16 + rB + dd * 8;
                int mh = rem >> 6, cc = rem & 63;
                int rowbase = ((bb * NM + mh) * SLEN + ti * 256 + pb) * HD + cc;
                #pragma unroll
                for (int ni = 0; ni < 8; ni++) {
                    int p = wc * 64 + ni * 8 + cB;
                    dst[rowbase + p * HD]       = acc[mi][ni][dd * 2];
                    dst[rowbase + (p + 1) * HD] = acc[mi][ni][dd * 2 + 1];
                }
            }
    } else {
        const float c1 = 0.9191450300180578f;   // 0.7 / sqrt(0.58)
        const float c2 = 0.3939192985791676f;   // 0.3 / sqrt(0.58)
        #pragma unroll
        for (int mi = 0; mi < 2; mi++)
            #pragma unroll
            for (int dd = 0; dd < 2; dd++) {
                int o = o0 + wr * 32 + mi * 16 + rB + dd * 8;
                int ib = bt * XSTRIDE + o * 256 + pb + wc * 64 + cB;
                #pragma unroll
                for (int ni = 0; ni < 8; ni++) {
                    int idx = ib + ni * 8;
                    Out[idx]     = Xres[idx] * c1 + acc[mi][ni][dd * 2] * c2;
                    Out[idx + 1] = Xres[idx + 1] * c1 + acc[mi][ni][dd * 2 + 1] * c2;
                }
            }
    }
}

// ---------------- K3: RoPE over frame index ----------------
__global__ __launch_bounds__(256) void rope_k() {
    int idx = blockIdx.x * 256 + threadIdx.x;
    int d2 = idx & 31;
    int s = (idx >> 5) & 2047;
    int bm = idx >> 16;
    int ti = s >> 8;
    float ang = (float)ti * __powf(10000.0f, -(float)d2 * (1.0f / 32.0f));
    float sn, cs;
    __sincosf(ang, &sn, &cs);
    int base = (bm * SLEN + s) * HD + d2;
    float q1 = g_q[base], q2 = g_q[base + 32];
    g_q[base]      = q1 * cs - q2 * sn;
    g_q[base + 32] = q1 * sn + q2 * cs;
    float k1 = g_k[base], k2 = g_k[base + 32];
    g_k[base]      = k1 * cs - k2 * sn;
    g_k[base + 32] = k1 * sn + k2 * cs;
}

// ---------------- K4: block-causal flash attention ----------------
__global__ __launch_bounds__(256) void flash_k() {
    __shared__ float Qs[64 * 68];
    __shared__ float Ks[32 * 68];
    __shared__ float Vs[32 * 68];
    __shared__ float Ps[64 * 36];

    const int tid = threadIdx.x;
    const int tx = tid & 15, ty = tid >> 4;
    const int qt = blockIdx.x, bm = blockIdx.y;
    const int s0 = qt * 64;
    const int fr = qt >> 2;
    const int nk = (fr + 1) * 256;

    const float* Qg = g_q + (bm * SLEN + s0) * HD;
    const float* Kg = g_k + bm * SLEN * HD;
    const float* Vg = g_v + bm * SLEN * HD;

    #pragma unroll
    for (int it = 0; it < 4; it++) {
        int slot = tid + it * 256;
        int r = slot >> 4, c4 = slot & 15;
        *(float4*)&Qs[r * 68 + c4 * 4] = *(const float4*)&Qg[r * 64 + c4 * 4];
    }

    float mrow[4], lrow[4];
    unsigned long long oac[4][2];
    #pragma unroll
    for (int ri = 0; ri < 4; ri++) {
        mrow[ri] = -1e30f; lrow[ri] = 0.f;
        oac[ri][0] = 0ULL; oac[ri][1] = 0ULL;
    }

    for (int k0 = 0; k0 < nk; k0 += 32) {
        __syncthreads();
        #pragma unroll
        for (int it = 0; it < 2; it++) {
            int slot = tid + it * 256;
            int r = slot >> 4, c4 = slot & 15;
            *(float4*)&Ks[r * 68 + c4 * 4] = *(const float4*)&Kg[(k0 + r) * 64 + c4 * 4];
            *(float4*)&Vs[r * 68 + c4 * 4] = *(const float4*)&Vg[(k0 + r) * 64 + c4 * 4];
        }
        __syncthreads();

        unsigned long long sac[4][2];
        #pragma unroll
        for (int ri = 0; ri < 4; ri++) { sac[ri][0] = 0ULL; sac[ri][1] = 0ULL; }
        #pragma unroll
        for (int c = 0; c < 64; c += 4) {
            float4 q4[4], k4[2];
            #pragma unroll
            for (int ri = 0; ri < 4; ri++) q4[ri] = *(const float4*)&Qs[(ty * 4 + ri) * 68 + c];
            #pragma unroll
            for (int ji = 0; ji < 2; ji++) k4[ji] = *(const float4*)&Ks[(tx + 16 * ji) * 68 + c];
            #pragma unroll
            for (int ri = 0; ri < 4; ri++) {
                #pragma unroll
                for (int ji = 0; ji < 2; ji++) {
                    ffma2(sac[ri][ji], flo(q4[ri]), flo(k4[ji]));
                    ffma2(sac[ri][ji], fhi(q4[ri]), fhi(k4[ji]));
                }
            }
        }
        float sc[4][2];
        #pragma unroll
        for (int ri = 0; ri < 4; ri++) {
            #pragma unroll
            for (int ji = 0; ji < 2; ji++) {
                float2 t = u2f(sac[ri][ji]);
                sc[ri][ji] = (t.x + t.y) * 0.125f;
            }
        }

        float pr[4][2];
        #pragma unroll
        for (int ri = 0; ri < 4; ri++) {
            float mx = fmaxf(sc[ri][0], sc[ri][1]);
            #pragma unroll
            for (int off = 8; off; off >>= 1) mx = fmaxf(mx, __shfl_xor_sync(0xffffffffu, mx, off));
            float mnew = fmaxf(mrow[ri], mx);
            float cr = __expf(mrow[ri] - mnew);
            mrow[ri] = mnew;
            float p0 = __expf(sc[ri][0] - mnew);
            float p1 = __expf(sc[ri][1] - mnew);
            pr[ri][0] = p0; pr[ri][1] = p1;
            float ps = p0 + p1;
            #pragma unroll
            for (int off = 8; off; off >>= 1) ps += __shfl_xor_sync(0xffffffffu, ps, off);
            lrow[ri] = lrow[ri] * cr + ps;
            unsigned long long cp = pack2(cr);
            fmul2(oac[ri][0], cp);
            fmul2(oac[ri][1], cp);
        }
        #pragma unroll
        for (int ri = 0; ri < 4; ri++) {
            Ps[(ty * 4 + ri) * 36 + tx]      = pr[ri][0];
            Ps[(ty * 4 + ri) * 36 + tx + 16] = pr[ri][1];
        }
        __syncwarp();

        #pragma unroll
        for (int j4 = 0; j4 < 32; j4 += 4) {
            float4 a4[4];
            #pragma unroll
            for (int ri = 0; ri < 4; ri++) a4[ri] = *(const float4*)&Ps[(ty * 4 + ri) * 36 + j4];
            #pragma unroll
            for (int jj = 0; jj < 4; jj++) {
                unsigned long long blo = *(const unsigned long long*)&Vs[(j4 + jj) * 68 + 2 * tx];
                unsigned long long bhi = *(const unsigned long long*)&Vs[(j4 + jj) * 68 + 2 * tx + 32];
                #pragma unroll
                for (int ri = 0; ri < 4; ri++) {
                    unsigned long long ap = pack2(f4get(a4[ri], jj));
                    ffma2(oac[ri][0], ap, blo);
                    ffma2(oac[ri][1], ap, bhi);
                }
            }
        }
    }

    __syncthreads();
    #pragma unroll
    for (int ri = 0; ri < 4; ri++) {
        float li = 1.0f / lrow[ri];
        float2 v0 = u2f(oac[ri][0]);
        float2 v1 = u2f(oac[ri][1]);
        int r = ty * 4 + ri;
        Qs[(2 * tx) * 68 + r]      = v0.x * li;
        Qs[(2 * tx + 1) * 68 + r]  = v0.y * li;
        Qs[(2 * tx + 32) * 68 + r] = v1.x * li;
        Qs[(2 * tx + 33) * 68 + r] = v1.y * li;
    }
    __syncthreads();

    const int bb = bm / NM, mh = bm - bb * NM;
    const int bt = bb * NT + fr;
    const int p0 = s0 & 255;
    int obase = bt * XSTRIDE + mh * 256 + p0;
    #pragma unroll
    for (int it = 0; it < 16; it++) {
        int slot = tid + it * 256;
        int ch = slot >> 6, pp = slot & 63;
        g_yt[obase + ch * 3072 + pp] = Qs[ch * 68 + pp];
    }
}

// ---------------- launch ----------------
extern "C" void kernel_launch(void* const* d_in, const int* in_sizes, int n_in,
                              void* d_out, int out_size) {
    const float* x = (const float*)d_in[0];
    const float* wqkv = (const float*)d_in[1];
    const float* wproj = (const float*)d_in[2];
    float* out = (float*)d_out;

    float* yt_ptr;
    cudaGetSymbolAddress((void**)&yt_ptr, g_yt);

    const int GSMEM = 2 * STAGE_BYTES;   // 70656 B double-buffered
    cudaFuncSetAttribute(gemm_f3<0>, cudaFuncAttributeMaxDynamicSharedMemorySize, GSMEM);
    cudaFuncSetAttribute(gemm_f3<1>, cudaFuncAttributeMaxDynamicSharedMemorySize, GSMEM);

    norm_k<<<C3 + CDIM, 256>>>(wqkv, wproj);
    gemm_f3<0><<<dim3(32, 18), 256, GSMEM>>>(x, nullptr, nullptr);
    rope_k<<<(NB * NM * SLEN * 32) / 256, 256>>>();
    flash_k<<<dim3(32, 24), 256>>>();
    gemm_f3<1><<<dim3(32, 6), 256, GSMEM>>>(yt_ptr, x, out);
}

// round 8
// speedup vs baseline: 1.3964x; 1.2240x over previous
#include <cuda_runtime.h>
#include <cuda_bf16.h>
#include <math.h>
#include <cstdint>

// ---------------------------------------------------------------------------
// VideoAttention: b=2, t=8, C=768, h=w=16 -> hw=256, S=2048, heads=12, c=64
//   K1 norm_k    : EDM2 MP weight norm -> fp32 normalized weights
//   K2 gemm_f3<0>: 3xTF32 HMMA GEMM (2304 x 4096 x 768) -> q, k fp32; v split tf32
//   K3 rope_k    : rotary over frame index; k -> tf32 hi/lo split
//   K4 flash_tc  : block-causal flash attention, 3xTF32 HMMA -> g_yt
//   K5 gemm_f3<1>: 3xTF32 HMMA proj GEMM + mp_sum residual -> out
// 3xTF32 everywhere: a = ah + al (tf32), C = AhBh + AhBl + AlBh (~1e-7 rel).
// ---------------------------------------------------------------------------

#define NB   2
#define NT   8
#define NM   12
#define HD   64
#define C3   2304
#define CDIM 768
#define SLEN 2048
#define BT   16
#define XSTRIDE 196608   // 768*256

__device__ float g_wqkv[C3 * CDIM];
__device__ float g_wproj[CDIM * CDIM];
__device__ float g_q[NB * NM * SLEN * HD];
__device__ float g_k[NB * NM * SLEN * HD];
__device__ uint32_t g_kh[NB * NM * SLEN * HD], g_kl[NB * NM * SLEN * HD];
__device__ uint32_t g_vh[NB * NM * SLEN * HD], g_vl[NB * NM * SLEN * HD];
__device__ float g_yt[BT * CDIM * 256];           // attn out, [bt][ch][p] fp32

// ======================= PTX helpers ===================
__device__ __forceinline__ uint32_t smem_to_u32(const void* p) {
    uint32_t a;
    asm("{ .reg .u64 t; cvta.to.shared.u64 t, %1; cvt.u32.u64 %0, t; }" : "=r"(a) : "l"(p));
    return a;
}
__device__ __forceinline__ float lds_f32(uint32_t addr) {
    float v;
    asm volatile("ld.shared.f32 %0, [%1];" : "=f"(v) : "r"(addr));
    return v;
}
__device__ __forceinline__ uint32_t lds_u32(uint32_t addr) {
    uint32_t v;
    asm volatile("ld.shared.b32 %0, [%1];" : "=r"(v) : "r"(addr));
    return v;
}
__device__ __forceinline__ void sts_f32(uint32_t addr, float v) {
    asm volatile("st.shared.f32 [%0], %1;" :: "r"(addr), "f"(v));
}
__device__ __forceinline__ void cp16(uint32_t dst, const void* src) {
    asm volatile("cp.async.cg.shared.global [%0], [%1], 16;" :: "r"(dst), "l"(src));
}
#define CP_COMMIT() asm volatile("cp.async.commit_group;" ::: "memory")
#define CP_WAIT(n)  asm volatile("cp.async.wait_group %0;" :: "n"(n) : "memory")

__device__ __forceinline__ uint32_t f2tf32(float a) {
    uint32_t r;
    asm("cvt.rna.tf32.f32 %0, %1;" : "=r"(r) : "f"(a));
    return r;
}
__device__ __forceinline__ void tf32_split(float a, uint32_t& h, uint32_t& l) {
    h = f2tf32(a);
    l = f2tf32(a - __uint_as_float(h));
}
__device__ __forceinline__ void mma_tf32(float (&d)[4], const uint32_t (&a)[4],
                                         uint32_t b0, uint32_t b1) {
    asm volatile("mma.sync.aligned.m16n8k8.row.col.f32.tf32.tf32.f32 "
                 "{%0,%1,%2,%3}, {%4,%5,%6,%7}, {%8,%9}, {%0,%1,%2,%3};"
                 : "+f"(d[0]), "+f"(d[1]), "+f"(d[2]), "+f"(d[3])
                 : "r"(a[0]), "r"(a[1]), "r"(a[2]), "r"(a[3]), "r"(b0), "r"(b1));
}

// ---------------- K1: weight normalization (fp32 out) ----------------
__global__ __launch_bounds__(256) void norm_k(const float* __restrict__ wqkv,
                                              const float* __restrict__ wproj) {
    int row = blockIdx.x;
    const float* src;
    float* dst;
    if (row < C3) { src = wqkv + row * CDIM;        dst = g_wqkv + row * CDIM; }
    else          { src = wproj + (row - C3) * CDIM; dst = g_wproj + (row - C3) * CDIM; }

    float ss = 0.f;
    for (int i = threadIdx.x; i < CDIM; i += 256) { float v = src[i]; ss = fmaf(v, v, ss); }
    #pragma unroll
    for (int off = 16; off; off >>= 1) ss += __shfl_xor_sync(0xffffffffu, ss, off);

    __shared__ float sred[8];
    __shared__ float sscale;
    if ((threadIdx.x & 31) == 0) sred[threadIdx.x >> 5] = ss;
    __syncthreads();
    if (threadIdx.x == 0) {
        float t = 0.f;
        #pragma unroll
        for (int i = 0; i < 8; i++) t += sred[i];
        sscale = 1.0f / (sqrtf(768.0f) * 1e-4f + sqrtf(t));
    }
    __syncthreads();
    float sc = sscale;
    for (int i = threadIdx.x; i < CDIM; i += 256) dst[i] = src[i] * sc;
}

// ---------------- K2/K5: 3xTF32 HMMA GEMM, 128x128 block tile --------------
#define A_PAD_W 36
#define B_PAD_W 132
#define A_BYTES (128 * A_PAD_W * 4)
#define STAGE_BYTES (A_BYTES + 32 * B_PAD_W * 4)

template <int EPI>
__global__ __launch_bounds__(256) void gemm_f3(const float* __restrict__ Bsrc,
                                               const float* __restrict__ Xres,
                                               float* __restrict__ Out) {
    extern __shared__ char smem[];
    const uint32_t sb = smem_to_u32(smem);
    const int tid = threadIdx.x, wid = tid >> 5, lid = tid & 31;
    const int o0 = blockIdx.y * 128;
    const int n0 = blockIdx.x * 128;
    const int bt = n0 >> 8;
    const int pb = n0 & 255;

    const float* Aw = (EPI == 0 ? g_wqkv : g_wproj) + o0 * CDIM;
    const float* Bg = Bsrc + bt * XSTRIDE + pb;

    float acc[2][8][4];
    #pragma unroll
    for (int mi = 0; mi < 2; mi++)
        #pragma unroll
        for (int ni = 0; ni < 8; ni++)
            #pragma unroll
            for (int d = 0; d < 4; d++) acc[mi][ni][d] = 0.f;

    const int wr = wid & 3, wc = wid >> 2;
    const int g = lid >> 2, tg = lid & 3;

    auto copy_stage = [&](int st, int kc) {
        uint32_t s0 = sb + st * STAGE_BYTES;
        #pragma unroll
        for (int i = 0; i < 4; i++) {
            int idx = tid + i * 256;
            int row = idx >> 3, u = idx & 7;
            cp16(s0 + row * (A_PAD_W * 4) + u * 16,
                 Aw + row * CDIM + kc + u * 4);
        }
        uint32_t sB0 = s0 + A_BYTES;
        #pragma unroll
        for (int i = 0; i < 4; i++) {
            int idx = tid + i * 256;
            int r = idx >> 5, u = idx & 31;
            cp16(sB0 + r * (B_PAD_W * 4) + u * 16,
                 Bg + (kc + r) * 256 + u * 4);
        }
        CP_COMMIT();
    };

    copy_stage(0, 0);
    int st = 0;
    for (int kc = 0; kc < CDIM; kc += 32, st ^= 1) {
        if (kc + 32 < CDIM) {
            copy_stage(st ^ 1, kc + 32);
            CP_WAIT(1);
        } else {
            CP_WAIT(0);
        }
        __syncthreads();

        const uint32_t sA = sb + st * STAGE_BYTES;
        const uint32_t sB = sA + A_BYTES;
        #pragma unroll
        for (int ks = 0; ks < 4; ks++) {
            const int kk = ks * 8;
            uint32_t ah[2][4], al[2][4];
            #pragma unroll
            for (int mi = 0; mi < 2; mi++) {
                uint32_t r0 = sA + (wr * 32 + mi * 16 + g) * (A_PAD_W * 4);
                uint32_t r8 = r0 + 8 * (A_PAD_W * 4);
                tf32_split(lds_f32(r0 + (kk + tg) * 4),     ah[mi][0], al[mi][0]);
                tf32_split(lds_f32(r8 + (kk + tg) * 4),     ah[mi][1], al[mi][1]);
                tf32_split(lds_f32(r0 + (kk + tg + 4) * 4), ah[mi][2], al[mi][2]);
                tf32_split(lds_f32(r8 + (kk + tg + 4) * 4), ah[mi][3], al[mi][3]);
            }
            #pragma unroll
            for (int ni = 0; ni < 8; ni++) {
                const int n = wc * 64 + ni * 8 + g;
                uint32_t b0h, b0l, b1h, b1l;
                tf32_split(lds_f32(sB + (kk + tg) * (B_PAD_W * 4) + n * 4), b0h, b0l);
                tf32_split(lds_f32(sB + (kk + tg + 4) * (B_PAD_W * 4) + n * 4), b1h, b1l);
                #pragma unroll
                for (int mi = 0; mi < 2; mi++) {
                    mma_tf32(acc[mi][ni], ah[mi], b0h, b1h);
                    mma_tf32(acc[mi][ni], ah[mi], b0l, b1l);
                    mma_tf32(acc[mi][ni], al[mi], b0h, b1h);
                }
            }
        }
        __syncthreads();
    }

    const int rB = g;
    const int cB = tg * 2;

    if (EPI == 0) {
        const int qi = blockIdx.y / 6;
        const int rem0 = o0 - qi * CDIM + wr * 32;
        const int bb = bt >> 3, ti = bt & 7;
        #pragma unroll
        for (int mi = 0; mi < 2; mi++)
            #pragma unroll
            for (int dd = 0; dd < 2; dd++) {
                int rem = rem0 + mi * 16 + rB + dd * 8;
                int mh = rem >> 6, cc = rem & 63;
                int rowbase = ((bb * NM + mh) * SLEN + ti * 256 + pb) * HD + cc;
                #pragma unroll
                for (int ni = 0; ni < 8; ni++) {
                    int p = wc * 64 + ni * 8 + cB;
                    float v0 = acc[mi][ni][dd * 2];
                    float v1 = acc[mi][ni][dd * 2 + 1];
                    if (qi == 0) {
                        g_q[rowbase + p * HD] = v0;
                        g_q[rowbase + (p + 1) * HD] = v1;
                    } else if (qi == 1) {
                        g_k[rowbase + p * HD] = v0;
                        g_k[rowbase + (p + 1) * HD] = v1;
                    } else {
                        uint32_t h, l;
                        tf32_split(v0, h, l);
                        g_vh[rowbase + p * HD] = h; g_vl[rowbase + p * HD] = l;
                        tf32_split(v1, h, l);
                        g_vh[rowbase + (p + 1) * HD] = h; g_vl[rowbase + (p + 1) * HD] = l;
                    }
                }
            }
    } else {
        const float c1 = 0.9191450300180578f;   // 0.7 / sqrt(0.58)
        const float c2 = 0.3939192985791676f;   // 0.3 / sqrt(0.58)
        #pragma unroll
        for (int mi = 0; mi < 2; mi++)
            #pragma unroll
            for (int dd = 0; dd < 2; dd++) {
                int o = o0 + wr * 32 + mi * 16 + rB + dd * 8;
                int ib = bt * XSTRIDE + o * 256 + pb + wc * 64 + cB;
                #pragma unroll
                for (int ni = 0; ni < 8; ni++) {
                    int idx = ib + ni * 8;
                    Out[idx]     = Xres[idx] * c1 + acc[mi][ni][dd * 2] * c2;
                    Out[idx + 1] = Xres[idx + 1] * c1 + acc[mi][ni][dd * 2 + 1] * c2;
                }
            }
    }
}

// ---------------- K3: RoPE over frame index; K -> tf32 split ----------------
__global__ __launch_bounds__(256) void rope_k() {
    int idx = blockIdx.x * 256 + threadIdx.x;
    int d2 = idx & 31;
    int s = (idx >> 5) & 2047;
    int bm = idx >> 16;
    int ti = s >> 8;
    float ang = (float)ti * __powf(10000.0f, -(float)d2 * (1.0f / 32.0f));
    float sn, cs;
    __sincosf(ang, &sn, &cs);
    int base = (bm * SLEN + s) * HD + d2;
    float q1 = g_q[base], q2 = g_q[base + 32];
    g_q[base]      = q1 * cs - q2 * sn;
    g_q[base + 32] = q1 * sn + q2 * cs;
    float k1 = g_k[base], k2 = g_k[base + 32];
    float kr1 = k1 * cs - k2 * sn;
    float kr2 = k1 * sn + k2 * cs;
    uint32_t h, l;
    tf32_split(kr1, h, l); g_kh[base] = h;      g_kl[base] = l;
    tf32_split(kr2, h, l); g_kh[base + 32] = h; g_kl[base + 32] = l;
}

// ---------------- K4: block-causal flash attention, 3xTF32 HMMA ------------
// grid (16 q-tiles of 128 rows, 24 bm). 8 warps; warp w owns q rows w*16..+16.
// 32-key chunks, double-buffered cp.async of pre-split Kh/Kl/Vh/Vl.
// smem: 2 stages x [Kh|Kl|Vh|Vl] (each 32x68 u32) = 69632 B, + per-warp P
// staging 8 x 16x36 f32 = 18432 B. Epilogue O transpose reuses stage region.
#define FS_STAGE 34816           // 4 * 32*68*4
#define FS_PLANE 8704            // 32*68*4
#define FS_PS    69632
#define FS_TOTAL (FS_PS + 8 * 2304)

__global__ __launch_bounds__(256) void flash_tc() {
    extern __shared__ char fsm[];
    const uint32_t sb = smem_to_u32(fsm);
    const int tid = threadIdx.x, w = tid >> 5, lid = tid & 31;
    const int g = lid >> 2, tg = lid & 3;
    const int qt = blockIdx.x, bm = blockIdx.y;
    const int s0 = qt * 128;
    const int fr = qt >> 1;
    const int nch = (fr + 1) * 8;        // 32-key chunks (frame-aligned causal)

    const uint32_t PS = sb + FS_PS + w * 2304;   // per-warp 16x36 f32

    const float* Qg = g_q + (bm * SLEN + s0 + w * 16) * HD;
    const uint32_t* Khg = g_kh + bm * SLEN * HD;
    const uint32_t* Klg = g_kl + bm * SLEN * HD;
    const uint32_t* Vhg = g_vh + bm * SLEN * HD;
    const uint32_t* Vlg = g_vl + bm * SLEN * HD;

    // register-resident Q fragments (split once)
    uint32_t qh[8][4], ql[8][4];
    #pragma unroll
    for (int ks = 0; ks < 8; ks++) {
        int c0 = ks * 8 + tg;
        tf32_split(Qg[g * 64 + c0],           qh[ks][0], ql[ks][0]);
        tf32_split(Qg[(g + 8) * 64 + c0],     qh[ks][1], ql[ks][1]);
        tf32_split(Qg[g * 64 + c0 + 4],       qh[ks][2], ql[ks][2]);
        tf32_split(Qg[(g + 8) * 64 + c0 + 4], qh[ks][3], ql[ks][3]);
    }

    float o[8][4];
    #pragma unroll
    for (int ct = 0; ct < 8; ct++)
        #pragma unroll
        for (int d = 0; d < 4; d++) o[ct][d] = 0.f;
    float m0 = -1e30f, m1 = -1e30f, l0 = 0.f, l1 = 0.f;

    auto stage = [&](int st, int k0) {
        uint32_t b0 = sb + st * FS_STAGE;
        #pragma unroll
        for (int i = 0; i < 2; i++) {
            int idx = tid + i * 256;          // 0..511
            int key = idx >> 4, c4 = idx & 15;
            uint32_t d = b0 + key * 272 + c4 * 16;
            int go = (k0 + key) * 64 + c4 * 4;
            cp16(d,                Khg + go);
            cp16(d + FS_PLANE,     Klg + go);
            cp16(d + 2 * FS_PLANE, Vhg + go);
            cp16(d + 3 * FS_PLANE, Vlg + go);
        }
        CP_COMMIT();
    };

    stage(0, 0);
    int st = 0;
    for (int ic = 0; ic < nch; ic++, st ^= 1) {
        if (ic + 1 < nch) {
            stage(st ^ 1, (ic + 1) * 32);
            CP_WAIT(1);
        } else {
            CP_WAIT(0);
        }
        __syncthreads();
        const uint32_t bK = sb + st * FS_STAGE;
        const uint32_t bV = bK + 2 * FS_PLANE;

        // ---- S = Q K^T (16 rows x 32 keys per warp) ----
        float s[4][4];
        #pragma unroll
        for (int nt = 0; nt < 4; nt++)
            #pragma unroll
            for (int d = 0; d < 4; d++) s[nt][d] = 0.f;
        #pragma unroll
        for (int ks = 0; ks < 8; ks++) {
            #pragma unroll
            for (int nt = 0; nt < 4; nt++) {
                uint32_t off = bK + (nt * 8 + g) * 272 + (ks * 8 + tg) * 4;
                uint32_t bh0 = lds_u32(off), bh1 = lds_u32(off + 16);
                uint32_t bl0 = lds_u32(off + FS_PLANE), bl1 = lds_u32(off + FS_PLANE + 16);
                mma_tf32(s[nt], qh[ks], bh0, bh1);
                mma_tf32(s[nt], qh[ks], bl0, bl1);
                mma_tf32(s[nt], ql[ks], bh0, bh1);
            }
        }

        // ---- online softmax (rows g and g+8; reduce over the 4 tg lanes) ----
        float mx0 = -1e30f, mx1 = -1e30f;
        #pragma unroll
        for (int nt = 0; nt < 4; nt++) {
            #pragma unroll
            for (int d = 0; d < 4; d++) s[nt][d] *= 0.125f;
            mx0 = fmaxf(mx0, fmaxf(s[nt][0], s[nt][1]));
            mx1 = fmaxf(mx1, fmaxf(s[nt][2], s[nt][3]));
        }
        mx0 = fmaxf(mx0, __shfl_xor_sync(0xffffffffu, mx0, 1));
        mx0 = fmaxf(mx0, __shfl_xor_sync(0xffffffffu, mx0, 2));
        mx1 = fmaxf(mx1, __shfl_xor_sync(0xffffffffu, mx1, 1));
        mx1 = fmaxf(mx1, __shfl_xor_sync(0xffffffffu, mx1, 2));
        float mn0 = fmaxf(m0, mx0), mn1 = fmaxf(m1, mx1);
        float cr0 = __expf(m0 - mn0), cr1 = __expf(m1 - mn1);
        m0 = mn0; m1 = mn1;
        float rs0 = 0.f, rs1 = 0.f;
        #pragma unroll
        for (int nt = 0; nt < 4; nt++) {
            s[nt][0] = __expf(s[nt][0] - mn0);
            s[nt][1] = __expf(s[nt][1] - mn0);
            s[nt][2] = __expf(s[nt][2] - mn1);
            s[nt][3] = __expf(s[nt][3] - mn1);
            rs0 += s[nt][0] + s[nt][1];
            rs1 += s[nt][2] + s[nt][3];
        }
        rs0 += __shfl_xor_sync(0xffffffffu, rs0, 1);
        rs0 += __shfl_xor_sync(0xffffffffu, rs0, 2);
        rs1 += __shfl_xor_sync(0xffffffffu, rs1, 1);
        rs1 += __shfl_xor_sync(0xffffffffu, rs1, 2);
        l0 = l0 * cr0 + rs0;
        l1 = l1 * cr1 + rs1;
        #pragma unroll
        for (int ct = 0; ct < 8; ct++) {
            o[ct][0] *= cr0; o[ct][1] *= cr0;
            o[ct][2] *= cr1; o[ct][3] *= cr1;
        }

        // ---- stage P (C-frag layout -> A-frag layout via padded smem) ----
        #pragma unroll
        for (int nt = 0; nt < 4; nt++) {
            uint32_t a0 = PS + g * 144 + (nt * 8 + 2 * tg) * 4;
            uint32_t a1 = PS + (g + 8) * 144 + (nt * 8 + 2 * tg) * 4;
            sts_f32(a0, s[nt][0]); sts_f32(a0 + 4, s[nt][1]);
            sts_f32(a1, s[nt][2]); sts_f32(a1 + 4, s[nt][3]);
        }
        __syncwarp();

        // ---- O += P V ----
        #pragma unroll
        for (int k2 = 0; k2 < 4; k2++) {
            uint32_t ph[4], pl[4];
            int kcol = k2 * 8 + tg;
            tf32_split(lds_f32(PS + g * 144 + kcol * 4),             ph[0], pl[0]);
            tf32_split(lds_f32(PS + (g + 8) * 144 + kcol * 4),       ph[1], pl[1]);
            tf32_split(lds_f32(PS + g * 144 + (kcol + 4) * 4),       ph[2], pl[2]);
            tf32_split(lds_f32(PS + (g + 8) * 144 + (kcol + 4) * 4), ph[3], pl[3]);
            #pragma unroll
            for (int ct = 0; ct < 8; ct++) {
                uint32_t voff = bV + (k2 * 8 + tg) * 272 + (ct * 8 + g) * 4;
                uint32_t vh0 = lds_u32(voff), vh1 = lds_u32(voff + 4 * 272);
                uint32_t vl0 = lds_u32(voff + FS_PLANE), vl1 = lds_u32(voff + FS_PLANE + 4 * 272);
                mma_tf32(o[ct], ph, vh0, vh1);
                mma_tf32(o[ct], ph, vl0, vl1);
                mma_tf32(o[ct], pl, vh0, vh1);
            }
        }
        __syncthreads();
    }

    // ---- epilogue: O /= l, transpose via smem (reuse stage area), write yt ----
    float li0 = 1.f / l0, li1 = 1.f / l1;
    #pragma unroll
    for (int ct = 0; ct < 8; ct++) {
        int c0 = ct * 8 + 2 * tg;
        int row0 = w * 16 + g, row1 = row0 + 8;
        sts_f32(sb + c0 * 528 + row0 * 4,       o[ct][0] * li0);
        sts_f32(sb + (c0 + 1) * 528 + row0 * 4, o[ct][1] * li0);
        sts_f32(sb + c0 * 528 + row1 * 4,       o[ct][2] * li1);
        sts_f32(sb + (c0 + 1) * 528 + row1 * 4, o[ct][3] * li1);
    }
    __syncthreads();
    const int bb = bm / NM, mh = bm - bb * NM;
    const int bt = bb * NT + fr;
    const int p0 = (qt & 1) * 128;
    const int obase = bt * XSTRIDE + mh * 256 + p0;
    #pragma unroll
    for (int it = 0; it < 32; it++) {
        int idx = tid + it * 256;       // 0..8191
        int c = idx >> 7, rr = idx & 127;
        g_yt[obase + c * 3072 + rr] = lds_f32(sb + c * 528 + rr * 4);
    }
}

// ---------------- launch ----------------
extern "C" void kernel_launch(void* const* d_in, const int* in_sizes, int n_in,
                              void* d_out, int out_size) {
    const float* x = (const float*)d_in[0];
    const float* wqkv = (const float*)d_in[1];
    const float* wproj = (const float*)d_in[2];
    float* out = (float*)d_out;

    float* yt_ptr;
    cudaGetSymbolAddress((void**)&yt_ptr, g_yt);

    const int GSMEM = 2 * STAGE_BYTES;
    cudaFuncSetAttribute(gemm_f3<0>, cudaFuncAttributeMaxDynamicSharedMemorySize, GSMEM);
    cudaFuncSetAttribute(gemm_f3<1>, cudaFuncAttributeMaxDynamicSharedMemorySize, GSMEM);
    cudaFuncSetAttribute(flash_tc, cudaFuncAttributeMaxDynamicSharedMemorySize, FS_TOTAL);

    norm_k<<<C3 + CDIM, 256>>>(wqkv, wproj);
    gemm_f3<0><<<dim3(32, 18), 256, GSMEM>>>(x, nullptr, nullptr);
    rope_k<<<(NB * NM * SLEN * 32) / 256, 256>>>();
    flash_tc<<<dim3(16, 24), 256, FS_TOTAL>>>();
    gemm_f3<1><<<dim3(32, 6), 256, GSMEM>>>(yt_ptr, x, out);
}

// round 9
// speedup vs baseline: 1.4370x; 1.0291x over previous
#include <cuda_runtime.h>
#include <cuda_bf16.h>
#include <math.h>
#include <cstdint>

// ---------------------------------------------------------------------------
// VideoAttention: b=2, t=8, C=768, h=w=16 -> hw=256, S=2048, heads=12, c=64
//   K1 norm_k    : EDM2 MP weight norm -> fp32 normalized weights
//   K2 gemm_f3<0>: 3xTF32 HMMA GEMM (2304 x 4096 x 768) -> q, k fp32; v split tf32
//   K3 rope_k    : rotary over frame index; k -> tf32 hi/lo split
//   K4 flash_tc  : block-causal flash attention, 3xTF32 HMMA -> g_yt
//                  (128-thr CTAs, 64 q-rows, 2 CTAs/SM, heavy-tiles-first)
//   K5 gemm_f3<1>: 3xTF32 HMMA proj GEMM + mp_sum residual -> out
// 3xTF32 everywhere: a = ah + al (tf32), C = AhBh + AhBl + AlBh (~1e-7 rel).
// ---------------------------------------------------------------------------

#define NB   2
#define NT   8
#define NM   12
#define HD   64
#define C3   2304
#define CDIM 768
#define SLEN 2048
#define BT   16
#define XSTRIDE 196608   // 768*256

__device__ float g_wqkv[C3 * CDIM];
__device__ float g_wproj[CDIM * CDIM];
__device__ float g_q[NB * NM * SLEN * HD];
__device__ float g_k[NB * NM * SLEN * HD];
__device__ uint32_t g_kh[NB * NM * SLEN * HD], g_kl[NB * NM * SLEN * HD];
__device__ uint32_t g_vh[NB * NM * SLEN * HD], g_vl[NB * NM * SLEN * HD];
__device__ float g_yt[BT * CDIM * 256];           // attn out, [bt][ch][p] fp32

// ======================= PTX helpers ===================
__device__ __forceinline__ uint32_t smem_to_u32(const void* p) {
    uint32_t a;
    asm("{ .reg .u64 t; cvta.to.shared.u64 t, %1; cvt.u32.u64 %0, t; }" : "=r"(a) : "l"(p));
    return a;
}
__device__ __forceinline__ float lds_f32(uint32_t addr) {
    float v;
    asm volatile("ld.shared.f32 %0, [%1];" : "=f"(v) : "r"(addr));
    return v;
}
__device__ __forceinline__ uint32_t lds_u32(uint32_t addr) {
    uint32_t v;
    asm volatile("ld.shared.b32 %0, [%1];" : "=r"(v) : "r"(addr));
    return v;
}
__device__ __forceinline__ void sts_f32(uint32_t addr, float v) {
    asm volatile("st.shared.f32 [%0], %1;" :: "r"(addr), "f"(v));
}
__device__ __forceinline__ void cp16(uint32_t dst, const void* src) {
    asm volatile("cp.async.cg.shared.global [%0], [%1], 16;" :: "r"(dst), "l"(src));
}
#define CP_COMMIT() asm volatile("cp.async.commit_group;" ::: "memory")
#define CP_WAIT(n)  asm volatile("cp.async.wait_group %0;" :: "n"(n) : "memory")

__device__ __forceinline__ uint32_t f2tf32(float a) {
    uint32_t r;
    asm("cvt.rna.tf32.f32 %0, %1;" : "=r"(r) : "f"(a));
    return r;
}
__device__ __forceinline__ void tf32_split(float a, uint32_t& h, uint32_t& l) {
    h = f2tf32(a);
    l = f2tf32(a - __uint_as_float(h));
}
__device__ __forceinline__ void mma_tf32(float (&d)[4], const uint32_t (&a)[4],
                                         uint32_t b0, uint32_t b1) {
    asm volatile("mma.sync.aligned.m16n8k8.row.col.f32.tf32.tf32.f32 "
                 "{%0,%1,%2,%3}, {%4,%5,%6,%7}, {%8,%9}, {%0,%1,%2,%3};"
                 : "+f"(d[0]), "+f"(d[1]), "+f"(d[2]), "+f"(d[3])
                 : "r"(a[0]), "r"(a[1]), "r"(a[2]), "r"(a[3]), "r"(b0), "r"(b1));
}

// ---------------- K1: weight normalization (fp32 out) ----------------
__global__ __launch_bounds__(256) void norm_k(const float* __restrict__ wqkv,
                                              const float* __restrict__ wproj) {
    int row = blockIdx.x;
    const float* src;
    float* dst;
    if (row < C3) { src = wqkv + row * CDIM;        dst = g_wqkv + row * CDIM; }
    else          { src = wproj + (row - C3) * CDIM; dst = g_wproj + (row - C3) * CDIM; }

    float ss = 0.f;
    for (int i = threadIdx.x; i < CDIM; i += 256) { float v = src[i]; ss = fmaf(v, v, ss); }
    #pragma unroll
    for (int off = 16; off; off >>= 1) ss += __shfl_xor_sync(0xffffffffu, ss, off);

    __shared__ float sred[8];
    __shared__ float sscale;
    if ((threadIdx.x & 31) == 0) sred[threadIdx.x >> 5] = ss;
    __syncthreads();
    if (threadIdx.x == 0) {
        float t = 0.f;
        #pragma unroll
        for (int i = 0; i < 8; i++) t += sred[i];
        sscale = 1.0f / (sqrtf(768.0f) * 1e-4f + sqrtf(t));
    }
    __syncthreads();
    float sc = sscale;
    for (int i = threadIdx.x; i < CDIM; i += 256) dst[i] = src[i] * sc;
}

// ---------------- K2/K5: 3xTF32 HMMA GEMM, 128x128 block tile --------------
#define A_PAD_W 36
#define B_PAD_W 132
#define A_BYTES (128 * A_PAD_W * 4)
#define STAGE_BYTES (A_BYTES + 32 * B_PAD_W * 4)

template <int EPI>
__global__ __launch_bounds__(256) void gemm_f3(const float* __restrict__ Bsrc,
                                               const float* __restrict__ Xres,
                                               float* __restrict__ Out) {
    extern __shared__ char smem[];
    const uint32_t sb = smem_to_u32(smem);
    const int tid = threadIdx.x, wid = tid >> 5, lid = tid & 31;
    const int o0 = blockIdx.y * 128;
    const int n0 = blockIdx.x * 128;
    const int bt = n0 >> 8;
    const int pb = n0 & 255;

    const float* Aw = (EPI == 0 ? g_wqkv : g_wproj) + o0 * CDIM;
    const float* Bg = Bsrc + bt * XSTRIDE + pb;

    float acc[2][8][4];
    #pragma unroll
    for (int mi = 0; mi < 2; mi++)
        #pragma unroll
        for (int ni = 0; ni < 8; ni++)
            #pragma unroll
            for (int d = 0; d < 4; d++) acc[mi][ni][d] = 0.f;

    const int wr = wid & 3, wc = wid >> 2;
    const int g = lid >> 2, tg = lid & 3;

    auto copy_stage = [&](int st, int kc) {
        uint32_t s0 = sb + st * STAGE_BYTES;
        #pragma unroll
        for (int i = 0; i < 4; i++) {
            int idx = tid + i * 256;
            int row = idx >> 3, u = idx & 7;
            cp16(s0 + row * (A_PAD_W * 4) + u * 16,
                 Aw + row * CDIM + kc + u * 4);
        }
        uint32_t sB0 = s0 + A_BYTES;
        #pragma unroll
        for (int i = 0; i < 4; i++) {
            int idx = tid + i * 256;
            int r = idx >> 5, u = idx & 31;
            cp16(sB0 + r * (B_PAD_W * 4) + u * 16,
                 Bg + (kc + r) * 256 + u * 4);
        }
        CP_COMMIT();
    };

    copy_stage(0, 0);
    int st = 0;
    for (int kc = 0; kc < CDIM; kc += 32, st ^= 1) {
        if (kc + 32 < CDIM) {
            copy_stage(st ^ 1, kc + 32);
            CP_WAIT(1);
        } else {
            CP_WAIT(0);
        }
        __syncthreads();

        const uint32_t sA = sb + st * STAGE_BYTES;
        const uint32_t sB = sA + A_BYTES;
        #pragma unroll
        for (int ks = 0; ks < 4; ks++) {
            const int kk = ks * 8;
            uint32_t ah[2][4], al[2][4];
            #pragma unroll
            for (int mi = 0; mi < 2; mi++) {
                uint32_t r0 = sA + (wr * 32 + mi * 16 + g) * (A_PAD_W * 4);
                uint32_t r8 = r0 + 8 * (A_PAD_W * 4);
                tf32_split(lds_f32(r0 + (kk + tg) * 4),     ah[mi][0], al[mi][0]);
                tf32_split(lds_f32(r8 + (kk + tg) * 4),     ah[mi][1], al[mi][1]);
                tf32_split(lds_f32(r0 + (kk + tg + 4) * 4), ah[mi][2], al[mi][2]);
                tf32_split(lds_f32(r8 + (kk + tg + 4) * 4), ah[mi][3], al[mi][3]);
            }
            #pragma unroll
            for (int ni = 0; ni < 8; ni++) {
                const int n = wc * 64 + ni * 8 + g;
                uint32_t b0h, b0l, b1h, b1l;
                tf32_split(lds_f32(sB + (kk + tg) * (B_PAD_W * 4) + n * 4), b0h, b0l);
                tf32_split(lds_f32(sB + (kk + tg + 4) * (B_PAD_W * 4) + n * 4), b1h, b1l);
                #pragma unroll
                for (int mi = 0; mi < 2; mi++) {
                    mma_tf32(acc[mi][ni], ah[mi], b0h, b1h);
                    mma_tf32(acc[mi][ni], ah[mi], b0l, b1l);
                    mma_tf32(acc[mi][ni], al[mi], b0h, b1h);
                }
            }
        }
        __syncthreads();
    }

    const int rB = g;
    const int cB = tg * 2;

    if (EPI == 0) {
        const int qi = blockIdx.y / 6;
        const int rem0 = o0 - qi * CDIM + wr * 32;
        const int bb = bt >> 3, ti = bt & 7;
        #pragma unroll
        for (int mi = 0; mi < 2; mi++)
            #pragma unroll
            for (int dd = 0; dd < 2; dd++) {
                int rem = rem0 + mi * 16 + rB + dd * 8;
                int mh = rem >> 6, cc = rem & 63;
                int rowbase = ((bb * NM + mh) * SLEN + ti * 256 + pb) * HD + cc;
                #pragma unroll
                for (int ni = 0; ni < 8; ni++) {
                    int p = wc * 64 + ni * 8 + cB;
                    float v0 = acc[mi][ni][dd * 2];
                    float v1 = acc[mi][ni][dd * 2 + 1];
                    if (qi == 0) {
                        g_q[rowbase + p * HD] = v0;
                        g_q[rowbase + (p + 1) * HD] = v1;
                    } else if (qi == 1) {
                        g_k[rowbase + p * HD] = v0;
                        g_k[rowbase + (p + 1) * HD] = v1;
                    } else {
                        uint32_t h, l;
                        tf32_split(v0, h, l);
                        g_vh[rowbase + p * HD] = h; g_vl[rowbase + p * HD] = l;
                        tf32_split(v1, h, l);
                        g_vh[rowbase + (p + 1) * HD] = h; g_vl[rowbase + (p + 1) * HD] = l;
                    }
                }
            }
    } else {
        const float c1 = 0.9191450300180578f;   // 0.7 / sqrt(0.58)
        const float c2 = 0.3939192985791676f;   // 0.3 / sqrt(0.58)
        #pragma unroll
        for (int mi = 0; mi < 2; mi++)
            #pragma unroll
            for (int dd = 0; dd < 2; dd++) {
                int o = o0 + wr * 32 + mi * 16 + rB + dd * 8;
                int ib = bt * XSTRIDE + o * 256 + pb + wc * 64 + cB;
                #pragma unroll
                for (int ni = 0; ni < 8; ni++) {
                    int idx = ib + ni * 8;
                    Out[idx]     = Xres[idx] * c1 + acc[mi][ni][dd * 2] * c2;
                    Out[idx + 1] = Xres[idx + 1] * c1 + acc[mi][ni][dd * 2 + 1] * c2;
                }
            }
    }
}

// ---------------- K3: RoPE over frame index; K -> tf32 split ----------------
__global__ __launch_bounds__(256) void rope_k() {
    int idx = blockIdx.x * 256 + threadIdx.x;
    int d2 = idx & 31;
    int s = (idx >> 5) & 2047;
    int bm = idx >> 16;
    int ti = s >> 8;
    float ang = (float)ti * __powf(10000.0f, -(float)d2 * (1.0f / 32.0f));
    float sn, cs;
    __sincosf(ang, &sn, &cs);
    int base = (bm * SLEN + s) * HD + d2;
    float q1 = g_q[base], q2 = g_q[base + 32];
    g_q[base]      = q1 * cs - q2 * sn;
    g_q[base + 32] = q1 * sn + q2 * cs;
    float k1 = g_k[base], k2 = g_k[base + 32];
    float kr1 = k1 * cs - k2 * sn;
    float kr2 = k1 * sn + k2 * cs;
    uint32_t h, l;
    tf32_split(kr1, h, l); g_kh[base] = h;      g_kl[base] = l;
    tf32_split(kr2, h, l); g_kh[base + 32] = h; g_kl[base + 32] = l;
}

// ---------------- K4: block-causal flash attention, 3xTF32 HMMA ------------
// grid (32 q-tiles of 64 rows heavy-first, 24 bm). 128 threads / 4 warps;
// warp w owns q rows w*16..+16. 32-key chunks, double-buffered cp.async of
// pre-split Kh/Kl/Vh/Vl. smem 78848 B -> 2 CTAs/SM (the R8 kernel's 256-thr
// 88KB config pinned occupancy to 1 CTA/SM and left tensor at 39.5%).
#define FS_STAGE 34816           // 4 * 32*68*4
#define FS_PLANE 8704            // 32*68*4
#define FS_PS    69632
#define FS_TOTAL (FS_PS + 4 * 2304)

__global__ __launch_bounds__(128) void flash_tc() {
    extern __shared__ char fsm[];
    const uint32_t sb = smem_to_u32(fsm);
    const int tid = threadIdx.x, w = tid >> 5, lid = tid & 31;
    const int g = lid >> 2, tg = lid & 3;
    const int qt = 31 - blockIdx.x;      // heavy causal tiles first
    const int bm = blockIdx.y;
    const int s0 = qt * 64;
    const int fr = qt >> 2;
    const int nch = (fr + 1) * 8;        // 32-key chunks (frame-aligned causal)

    const uint32_t PS = sb + FS_PS + w * 2304;   // per-warp 16x36 f32

    const float* Qg = g_q + (bm * SLEN + s0 + w * 16) * HD;
    const uint32_t* Khg = g_kh + bm * SLEN * HD;
    const uint32_t* Klg = g_kl + bm * SLEN * HD;
    const uint32_t* Vhg = g_vh + bm * SLEN * HD;
    const uint32_t* Vlg = g_vl + bm * SLEN * HD;

    // register-resident Q fragments (split once)
    uint32_t qh[8][4], ql[8][4];
    #pragma unroll
    for (int ks = 0; ks < 8; ks++) {
        int c0 = ks * 8 + tg;
        tf32_split(Qg[g * 64 + c0],           qh[ks][0], ql[ks][0]);
        tf32_split(Qg[(g + 8) * 64 + c0],     qh[ks][1], ql[ks][1]);
        tf32_split(Qg[g * 64 + c0 + 4],       qh[ks][2], ql[ks][2]);
        tf32_split(Qg[(g + 8) * 64 + c0 + 4], qh[ks][3], ql[ks][3]);
    }

    float o[8][4];
    #pragma unroll
    for (int ct = 0; ct < 8; ct++)
        #pragma unroll
        for (int d = 0; d < 4; d++) o[ct][d] = 0.f;
    float m0 = -1e30f, m1 = -1e30f, l0 = 0.f, l1 = 0.f;

    auto stage = [&](int st, int k0) {
        uint32_t b0 = sb + st * FS_STAGE;
        #pragma unroll
        for (int i = 0; i < 4; i++) {
            int idx = tid + i * 128;          // 0..511
            int key = idx >> 4, c4 = idx & 15;
            uint32_t d = b0 + key * 272 + c4 * 16;
            int go = (k0 + key) * 64 + c4 * 4;
            cp16(d,                Khg + go);
            cp16(d + FS_PLANE,     Klg + go);
            cp16(d + 2 * FS_PLANE, Vhg + go);
            cp16(d + 3 * FS_PLANE, Vlg + go);
        }
        CP_COMMIT();
    };

    stage(0, 0);
    int st = 0;
    for (int ic = 0; ic < nch; ic++, st ^= 1) {
        if (ic + 1 < nch) {
            stage(st ^ 1, (ic + 1) * 32);
            CP_WAIT(1);
        } else {
            CP_WAIT(0);
        }
        __syncthreads();
        const uint32_t bK = sb + st * FS_STAGE;
        const uint32_t bV = bK + 2 * FS_PLANE;

        // ---- S = Q K^T (16 rows x 32 keys per warp) ----
        float s[4][4];
        #pragma unroll
        for (int nt = 0; nt < 4; nt++)
            #pragma unroll
            for (int d = 0; d < 4; d++) s[nt][d] = 0.f;
        #pragma unroll
        for (int ks = 0; ks < 8; ks++) {
            #pragma unroll
            for (int nt = 0; nt < 4; nt++) {
                uint32_t off = bK + (nt * 8 + g) * 272 + (ks * 8 + tg) * 4;
                uint32_t bh0 = lds_u32(off), bh1 = lds_u32(off + 16);
                uint32_t bl0 = lds_u32(off + FS_PLANE), bl1 = lds_u32(off + FS_PLANE + 16);
                mma_tf32(s[nt], qh[ks], bh0, bh1);
                mma_tf32(s[nt], qh[ks], bl0, bl1);
                mma_tf32(s[nt], ql[ks], bh0, bh1);
            }
        }

        // ---- online softmax (rows g and g+8; reduce over the 4 tg lanes) ----
        float mx0 = -1e30f, mx1 = -1e30f;
        #pragma unroll
        for (int nt = 0; nt < 4; nt++) {
            #pragma unroll
            for (int d = 0; d < 4; d++) s[nt][d] *= 0.125f;
            mx0 = fmaxf(mx0, fmaxf(s[nt][0], s[nt][1]));
            mx1 = fmaxf(mx1, fmaxf(s[nt][2], s[nt][3]));
        }
        mx0 = fmaxf(mx0, __shfl_xor_sync(0xffffffffu, mx0, 1));
        mx0 = fmaxf(mx0, __shfl_xor_sync(0xffffffffu, mx0, 2));
        mx1 = fmaxf(mx1, __shfl_xor_sync(0xffffffffu, mx1, 1));
        mx1 = fmaxf(mx1, __shfl_xor_sync(0xffffffffu, mx1, 2));
        float mn0 = fmaxf(m0, mx0), mn1 = fmaxf(m1, mx1);
        float cr0 = __expf(m0 - mn0), cr1 = __expf(m1 - mn1);
        m0 = mn0; m1 = mn1;
        float rs0 = 0.f, rs1 = 0.f;
        #pragma unroll
        for (int nt = 0; nt < 4; nt++) {
            s[nt][0] = __expf(s[nt][0] - mn0);
            s[nt][1] = __expf(s[nt][1] - mn0);
            s[nt][2] = __expf(s[nt][2] - mn1);
            s[nt][3] = __expf(s[nt][3] - mn1);
            rs0 += s[nt][0] + s[nt][1];
            rs1 += s[nt][2] + s[nt][3];
        }
        rs0 += __shfl_xor_sync(0xffffffffu, rs0, 1);
        rs0 += __shfl_xor_sync(0xffffffffu, rs0, 2);
        rs1 += __shfl_xor_sync(0xffffffffu, rs1, 1);
        rs1 += __shfl_xor_sync(0xffffffffu, rs1, 2);
        l0 = l0 * cr0 + rs0;
        l1 = l1 * cr1 + rs1;
        #pragma unroll
        for (int ct = 0; ct < 8; ct++) {
            o[ct][0] *= cr0; o[ct][1] *= cr0;
            o[ct][2] *= cr1; o[ct][3] *= cr1;
        }

        // ---- stage P (C-frag layout -> A-frag layout via padded smem) ----
        #pragma unroll
        for (int nt = 0; nt < 4; nt++) {
            uint32_t a0 = PS + g * 144 + (nt * 8 + 2 * tg) * 4;
            uint32_t a1 = PS + (g + 8) * 144 + (nt * 8 + 2 * tg) * 4;
            sts_f32(a0, s[nt][0]); sts_f32(a0 + 4, s[nt][1]);
            sts_f32(a1, s[nt][2]); sts_f32(a1 + 4, s[nt][3]);
        }
        __syncwarp();

        // ---- O += P V ----
        #pragma unroll
        for (int k2 = 0; k2 < 4; k2++) {
            uint32_t ph[4], pl[4];
            int kcol = k2 * 8 + tg;
            tf32_split(lds_f32(PS + g * 144 + kcol * 4),             ph[0], pl[0]);
            tf32_split(lds_f32(PS + (g + 8) * 144 + kcol * 4),       ph[1], pl[1]);
            tf32_split(lds_f32(PS + g * 144 + (kcol + 4) * 4),       ph[2], pl[2]);
            tf32_split(lds_f32(PS + (g + 8) * 144 + (kcol + 4) * 4), ph[3], pl[3]);
            #pragma unroll
            for (int ct = 0; ct < 8; ct++) {
                uint32_t voff = bV + (k2 * 8 + tg) * 272 + (ct * 8 + g) * 4;
                uint32_t vh0 = lds_u32(voff), vh1 = lds_u32(voff + 4 * 272);
                uint32_t vl0 = lds_u32(voff + FS_PLANE), vl1 = lds_u32(voff + FS_PLANE + 4 * 272);
                mma_tf32(o[ct], ph, vh0, vh1);
                mma_tf32(o[ct], ph, vl0, vl1);
                mma_tf32(o[ct], pl, vh0, vh1);
            }
        }
        __syncthreads();
    }

    // ---- epilogue: O /= l, transpose via smem (reuse stage area), write yt ----
    float li0 = 1.f / l0, li1 = 1.f / l1;
    #pragma unroll
    for (int ct = 0; ct < 8; ct++) {
        int c0 = ct * 8 + 2 * tg;                // channel 0..63
        int row0 = w * 16 + g, row1 = row0 + 8;  // tile-local q row 0..63
        sts_f32(sb + c0 * 272 + row0 * 4,       o[ct][0] * li0);
        sts_f32(sb + (c0 + 1) * 272 + row0 * 4, o[ct][1] * li0);
        sts_f32(sb + c0 * 272 + row1 * 4,       o[ct][2] * li1);
        sts_f32(sb + (c0 + 1) * 272 + row1 * 4, o[ct][3] * li1);
    }
    __syncthreads();
    const int bb = bm / NM, mh = bm - bb * NM;
    const int bt = bb * NT + fr;
    const int p0 = (qt & 3) * 64;
    const int obase = bt * XSTRIDE + mh * 256 + p0;
    #pragma unroll
    for (int it = 0; it < 32; it++) {
        int idx = tid + it * 128;       // 0..4095
        int c = idx >> 6, rr = idx & 63;
        g_yt[obase + c * 3072 + rr] = lds_f32(sb + c * 272 + rr * 4);
    }
}

// ---------------- launch ----------------
extern "C" void kernel_launch(void* const* d_in, const int* in_sizes, int n_in,
                              void* d_out, int out_size) {
    const float* x = (const float*)d_in[0];
    const float* wqkv = (const float*)d_in[1];
    const float* wproj = (const float*)d_in[2];
    float* out = (float*)d_out;

    float* yt_ptr;
    cudaGetSymbolAddress((void**)&yt_ptr, g_yt);

    const int GSMEM = 2 * STAGE_BYTES;
    cudaFuncSetAttribute(gemm_f3<0>, cudaFuncAttributeMaxDynamicSharedMemorySize, GSMEM);
    cudaFuncSetAttribute(gemm_f3<1>, cudaFuncAttributeMaxDynamicSharedMemorySize, GSMEM);
    cudaFuncSetAttribute(flash_tc, cudaFuncAttributeMaxDynamicSharedMemorySize, FS_TOTAL);

    norm_k<<<C3 + CDIM, 256>>>(wqkv, wproj);
    gemm_f3<0><<<dim3(32, 18), 256, GSMEM>>>(x, nullptr, nullptr);
    rope_k<<<(NB * NM * SLEN * 32) / 256, 256>>>();
    flash_tc<<<dim3(32, 24), 128, FS_TOTAL>>>();
    gemm_f3<1><<<dim3(32, 6), 256, GSMEM>>>(yt_ptr, x, out);
}